// round 1
// baseline (speedup 1.0000x reference)
#include <cuda_runtime.h>

// ---------------- problem constants ----------------
#define BATCH 2048
#define INSTN 2
#define HAE   16384
#define DIN   1024
#define NROWS (BATCH*INSTN)            // 4096
#define HTOT  (BATCH*INSTN*HAE)        // 67,108,864
#define KSEL  (BATCH*INSTN*64)         // 262,144
#define XPEL  (BATCH*INSTN*DIN)        // 4,194,304
#define ROWCAP 1024
#define CANDCAP 65536

// ---------------- scratch (device globals; no allocations allowed) ------
__device__ float     g_WdT[(size_t)INSTN*HAE*DIN];   // 134MB transposed W_dec
__device__ unsigned  g_hist1[2048];
__device__ unsigned  g_hist2[2048];
__device__ unsigned  g_hist3[1024];
__device__ unsigned  g_sel[8];       // [0]=b1 [1]=need1 [2]=b2 [3]=need2 [4]=thr_bits [5]=tie_cutoff
__device__ unsigned  g_cand_cnt;
__device__ unsigned  g_cand_bits[CANDCAP];
__device__ unsigned  g_cand_idx[CANDCAP];
__device__ int       g_row_cnt[NROWS];
__device__ int       g_row_j[(size_t)NROWS*ROWCAP];
__device__ float     g_row_v[(size_t)NROWS*ROWCAP];

// ---------------- f32x2 packed FMA helpers (sm_103a FFMA2) --------------
__device__ __forceinline__ unsigned long long pk2(float x, float y) {
    unsigned long long r;
    asm("mov.b64 %0, {%1, %2};" : "=l"(r) : "f"(x), "f"(y));
    return r;
}
__device__ __forceinline__ void fma2(unsigned long long &c,
                                     unsigned long long a,
                                     unsigned long long b) {
    asm("fma.rn.f32x2 %0, %1, %2, %0;" : "+l"(c) : "l"(a), "l"(b));
}
__device__ __forceinline__ float2 upk(unsigned long long c) {
    float2 f;
    asm("mov.b64 {%0, %1}, %2;" : "=f"(f.x), "=f"(f.y) : "l"(c));
    return f;
}

// ---------------- reset (runs every launch; graph-replay safe) ----------
__global__ void reset_k() {
    int t = threadIdx.x;
    for (int s = t; s < 2048; s += 1024) g_hist1[s] = 0;
    for (int s = t; s < 2048; s += 1024) g_hist2[s] = 0;
    for (int s = t; s < 1024; s += 1024) g_hist3[s] = 0;
    for (int s = t; s < NROWS; s += 1024) g_row_cnt[s] = 0;
    if (t == 0) g_cand_cnt = 0;
}

// ---------------- W_dec transpose: [i][a][h] -> [i][h][a] ----------------
__global__ void transpose_k(const float* __restrict__ Wd) {
    __shared__ float tile[32][33];
    int i  = blockIdx.z;
    int h0 = blockIdx.x << 5;
    int a0 = blockIdx.y << 5;
    const float* src = Wd + (size_t)i * DIN * HAE;
    #pragma unroll
    for (int r = threadIdx.y; r < 32; r += 8)
        tile[r][threadIdx.x] = src[(size_t)(a0 + r) * HAE + h0 + threadIdx.x];
    __syncthreads();
    float* dst = g_WdT + (size_t)i * HAE * DIN;
    #pragma unroll
    for (int r = threadIdx.y; r < 32; r += 8)
        dst[(size_t)(h0 + r) * DIN + a0 + threadIdx.x] = tile[threadIdx.x][r];
}

// ---------------- encoder GEMM: h = relu(x @ W_enc^T + b_enc) ------------
// 128x128 tile, BK=16, 256 threads, 8x8 micro-tile via packed f32x2 FMA.
// Fused: histogram of top-11 float bits of positive outputs (radix pass 1).
__global__ __launch_bounds__(256, 2)
void enc_gemm(const float* __restrict__ X, const float* __restrict__ W,
              const float* __restrict__ benc, float* __restrict__ hout)
{
    const int inst  = blockIdx.z;
    const int mBase = blockIdx.y << 7;   // over BATCH=2048
    const int nBase = blockIdx.x << 7;   // over HAE=16384

    __shared__ float As[16][128];
    __shared__ float Bs[16][128];
    __shared__ unsigned shist[2048];

    const int tid = threadIdx.x;
    for (int s = tid; s < 2048; s += 256) shist[s] = 0;

    const int lrow = tid >> 1;           // 0..127
    const int lk0  = (tid & 1) << 3;     // 0 or 8

    const float* Ag = X + (size_t)(mBase + lrow) * (INSTN * DIN) + inst * DIN + lk0;
    const float* Bg = W + ((size_t)inst * HAE + nBase + lrow) * DIN + lk0;

    const int tm = tid >> 4, tn = tid & 15;

    unsigned long long c[8][4];
    #pragma unroll
    for (int i = 0; i < 8; i++)
        #pragma unroll
        for (int j = 0; j < 4; j++) c[i][j] = 0ull;

    for (int kt = 0; kt < DIN / 16; kt++) {
        float4 a0 = *(const float4*)(Ag + kt * 16);
        float4 a1 = *(const float4*)(Ag + kt * 16 + 4);
        float4 b0 = *(const float4*)(Bg + kt * 16);
        float4 b1 = *(const float4*)(Bg + kt * 16 + 4);
        __syncthreads();
        As[lk0+0][lrow] = a0.x; As[lk0+1][lrow] = a0.y;
        As[lk0+2][lrow] = a0.z; As[lk0+3][lrow] = a0.w;
        As[lk0+4][lrow] = a1.x; As[lk0+5][lrow] = a1.y;
        As[lk0+6][lrow] = a1.z; As[lk0+7][lrow] = a1.w;
        Bs[lk0+0][lrow] = b0.x; Bs[lk0+1][lrow] = b0.y;
        Bs[lk0+2][lrow] = b0.z; Bs[lk0+3][lrow] = b0.w;
        Bs[lk0+4][lrow] = b1.x; Bs[lk0+5][lrow] = b1.y;
        Bs[lk0+6][lrow] = b1.z; Bs[lk0+7][lrow] = b1.w;
        __syncthreads();

        #pragma unroll
        for (int k = 0; k < 16; k++) {
            float4 af0 = *(const float4*)&As[k][tm << 3];
            float4 af1 = *(const float4*)&As[k][(tm << 3) + 4];
            double2 bd0 = *(const double2*)&Bs[k][tn << 3];
            double2 bd1 = *(const double2*)&Bs[k][(tn << 3) + 4];
            unsigned long long bp0 = __double_as_longlong(bd0.x);
            unsigned long long bp1 = __double_as_longlong(bd0.y);
            unsigned long long bp2 = __double_as_longlong(bd1.x);
            unsigned long long bp3 = __double_as_longlong(bd1.y);
            float av[8] = {af0.x, af0.y, af0.z, af0.w, af1.x, af1.y, af1.z, af1.w};
            #pragma unroll
            for (int i = 0; i < 8; i++) {
                unsigned long long ap = pk2(av[i], av[i]);
                fma2(c[i][0], ap, bp0);
                fma2(c[i][1], ap, bp1);
                fma2(c[i][2], ap, bp2);
                fma2(c[i][3], ap, bp3);
            }
        }
    }

    // epilogue: bias + relu + store + histogram
    float bias[8];
    const float* bb = benc + (size_t)inst * HAE + nBase + (tn << 3);
    #pragma unroll
    for (int j = 0; j < 8; j++) bias[j] = bb[j];

    #pragma unroll
    for (int i = 0; i < 8; i++) {
        float vv[8];
        #pragma unroll
        for (int j = 0; j < 4; j++) {
            float2 f = upk(c[i][j]);
            vv[2*j]   = fmaxf(f.x + bias[2*j],   0.0f);
            vv[2*j+1] = fmaxf(f.y + bias[2*j+1], 0.0f);
        }
        #pragma unroll
        for (int l = 0; l < 8; l++)
            if (vv[l] > 0.0f) atomicAdd(&shist[__float_as_uint(vv[l]) >> 21], 1u);
        float* outRow = hout + (size_t)(mBase + (tm << 3) + i) * (INSTN * HAE)
                             + (size_t)inst * HAE + nBase + (tn << 3);
        float4 o0 = make_float4(vv[0], vv[1], vv[2], vv[3]);
        float4 o1 = make_float4(vv[4], vv[5], vv[6], vv[7]);
        *(float4*)(outRow)     = o0;
        *(float4*)(outRow + 4) = o1;
    }
    __syncthreads();
    for (int s = tid; s < 2048; s += 256) {
        unsigned cnt = shist[s];
        if (cnt) atomicAdd(&g_hist1[s], cnt);
    }
}

// ---------------- radix-select level 1: pick bin of top-11 bits ----------
__global__ void select1_k() {
    unsigned cum = 0;
    for (int b = 2047; b >= 0; b--) {
        unsigned cnt = g_hist1[b];
        if (cum + cnt >= (unsigned)KSEL) {
            g_sel[0] = (unsigned)b;
            g_sel[1] = (unsigned)KSEL - cum;
            return;
        }
        cum += cnt;
    }
    g_sel[0] = 0; g_sel[1] = 1;  // unreachable fallback
}

// ---------------- radix pass 2: histogram bits [20:10] within bin b1 -----
__global__ void pass2_k(const float* __restrict__ h) {
    unsigned b1 = g_sel[0];
    int stride = gridDim.x * blockDim.x;
    for (int q = blockIdx.x * blockDim.x + threadIdx.x; q < HTOT / 4; q += stride) {
        float4 v = *(const float4*)(h + (size_t)q * 4);
        unsigned u;
        u = __float_as_uint(v.x); if (v.x > 0.0f && (u >> 21) == b1) atomicAdd(&g_hist2[(u >> 10) & 2047], 1u);
        u = __float_as_uint(v.y); if (v.y > 0.0f && (u >> 21) == b1) atomicAdd(&g_hist2[(u >> 10) & 2047], 1u);
        u = __float_as_uint(v.z); if (v.z > 0.0f && (u >> 21) == b1) atomicAdd(&g_hist2[(u >> 10) & 2047], 1u);
        u = __float_as_uint(v.w); if (v.w > 0.0f && (u >> 21) == b1) atomicAdd(&g_hist2[(u >> 10) & 2047], 1u);
    }
}

__global__ void select2_k() {
    unsigned need = g_sel[1];
    unsigned cum = 0;
    for (int b = 2047; b >= 0; b--) {
        unsigned cnt = g_hist2[b];
        if (cum + cnt >= need) {
            g_sel[2] = (unsigned)b;
            g_sel[3] = need - cum;
            return;
        }
        cum += cnt;
    }
    g_sel[2] = 0; g_sel[3] = 1;
}

// ---------------- radix pass 3: low 10 bits within 22-bit prefix ---------
__global__ void pass3_k(const float* __restrict__ h) {
    unsigned pre = (g_sel[0] << 11) | g_sel[2];
    int stride = gridDim.x * blockDim.x;
    for (int q = blockIdx.x * blockDim.x + threadIdx.x; q < HTOT / 4; q += stride) {
        float4 v = *(const float4*)(h + (size_t)q * 4);
        float vl[4] = {v.x, v.y, v.z, v.w};
        #pragma unroll
        for (int l = 0; l < 4; l++) {
            unsigned u = __float_as_uint(vl[l]);
            if (vl[l] > 0.0f && (u >> 10) == pre) {
                atomicAdd(&g_hist3[u & 1023], 1u);
                unsigned p = atomicAdd(&g_cand_cnt, 1u);
                if (p < CANDCAP) { g_cand_bits[p] = u; g_cand_idx[p] = (unsigned)(q * 4 + l); }
            }
        }
    }
}

// ---------------- final select: exact threshold + stable tie cutoff ------
__global__ void select3_k() {
    unsigned need = g_sel[3];
    unsigned cum = 0;
    unsigned b3 = 0;
    for (int b = 1023; b >= 0; b--) {
        unsigned cnt = g_hist3[b];
        if (cum + cnt >= need) { b3 = (unsigned)b; break; }
        cum += cnt;
    }
    unsigned thr = (g_sel[0] << 21) | (g_sel[2] << 10) | b3;
    unsigned T = need - cum;   // how many elements EQUAL to thr to keep (>=1)
    g_sel[4] = thr;

    // ties: keep the T lowest flat indices (matches jax top_k stability)
    unsigned n = g_cand_cnt; if (n > CANDCAP) n = CANDCAP;
    unsigned idxs[256];
    unsigned m = 0;
    for (unsigned p = 0; p < n; p++)
        if (g_cand_bits[p] == thr) { if (m < 256) idxs[m] = g_cand_idx[p]; m++; }
    if (m <= T) { g_sel[5] = 0xFFFFFFFFu; return; }
    if (m > 256) m = 256;
    // partial selection sort for T-th smallest index
    for (unsigned r = 0; r < T; r++) {
        unsigned mn = r;
        for (unsigned s = r + 1; s < m; s++)
            if (idxs[s] < idxs[mn]) mn = s;
        unsigned tmp = idxs[r]; idxs[r] = idxs[mn]; idxs[mn] = tmp;
    }
    g_sel[5] = idxs[T - 1];
}

// ---------------- apply: zero non-kept, build per-row CSR of kept --------
__global__ void apply_k(float* __restrict__ h) {
    unsigned thr = g_sel[4];
    unsigned cut = g_sel[5];
    int stride = gridDim.x * blockDim.x;
    for (int q = blockIdx.x * blockDim.x + threadIdx.x; q < HTOT / 4; q += stride) {
        float4 v = *(float4*)(h + (size_t)q * 4);
        float vl[4] = {v.x, v.y, v.z, v.w};
        #pragma unroll
        for (int l = 0; l < 4; l++) {
            unsigned idx = (unsigned)(q * 4 + l);
            unsigned u = __float_as_uint(vl[l]);
            bool keep = (vl[l] > 0.0f) && (u > thr || (u == thr && idx <= cut));
            if (keep) {
                int row = (int)(idx >> 14);      // /HAE
                int j   = (int)(idx & 16383);
                int p = atomicAdd(&g_row_cnt[row], 1);
                if (p < ROWCAP) {
                    g_row_j[(size_t)row * ROWCAP + p] = j;
                    g_row_v[(size_t)row * ROWCAP + p] = vl[l];
                }
            } else {
                vl[l] = 0.0f;
            }
        }
        v.x = vl[0]; v.y = vl[1]; v.z = vl[2]; v.w = vl[3];
        *(float4*)(h + (size_t)q * 4) = v;
    }
}

// ---------------- sparse decoder: x' = relu(h_sparse @ W_dec^T + b) ------
__global__ void decoder_k(const float* __restrict__ bdec, float* __restrict__ xout) {
    int row = blockIdx.x;          // row = b*2 + i
    int inst = row & 1;
    int t = threadIdx.x;           // 256 threads, 4 outputs each
    int n = g_row_cnt[row];
    if (n > ROWCAP) n = ROWCAP;

    float acc[4];
    #pragma unroll
    for (int s = 0; s < 4; s++) acc[s] = bdec[inst * DIN + t + s * 256];

    const float* WT = g_WdT + (size_t)inst * HAE * DIN;
    const int* jl = g_row_j + (size_t)row * ROWCAP;
    const float* vl = g_row_v + (size_t)row * ROWCAP;
    for (int e = 0; e < n; e++) {
        int j = jl[e];
        float val = vl[e];
        const float* col = WT + (size_t)j * DIN;
        #pragma unroll
        for (int s = 0; s < 4; s++)
            acc[s] = fmaf(val, col[t + s * 256], acc[s]);
    }
    #pragma unroll
    for (int s = 0; s < 4; s++)
        xout[(size_t)row * DIN + t + s * 256] = fmaxf(acc[s], 0.0f);
}

// ---------------- launch --------------------------------------------------
extern "C" void kernel_launch(void* const* d_in, const int* in_sizes, int n_in,
                              void* d_out, int out_size) {
    (void)in_sizes; (void)n_in; (void)out_size;
    const float* x    = (const float*)d_in[0];
    const float* Wenc = (const float*)d_in[1];
    const float* Wdec = (const float*)d_in[2];
    const float* benc = (const float*)d_in[3];
    const float* bdec = (const float*)d_in[4];
    float* xout = (float*)d_out;               // x_prime: [2048,2,1024]
    float* hout = xout + XPEL;                 // h:       [2048,2,16384]

    reset_k<<<1, 1024>>>();
    transpose_k<<<dim3(HAE / 32, DIN / 32, INSTN), dim3(32, 8)>>>(Wdec);
    enc_gemm<<<dim3(HAE / 128, BATCH / 128, INSTN), 256>>>(x, Wenc, benc, hout);
    select1_k<<<1, 1>>>();
    pass2_k<<<4096, 256>>>(hout);
    select2_k<<<1, 1>>>();
    pass3_k<<<4096, 256>>>(hout);
    select3_k<<<1, 1>>>();
    apply_k<<<4096, 256>>>(hout);
    decoder_k<<<NROWS, 256>>>(bdec, xout);
}